// round 2
// baseline (speedup 1.0000x reference)
#include <cuda_runtime.h>
#include <math.h>

#define HID   246
#define NMAX  50000
#define EMAX  320000

// ---------------- device-global scratch (no allocation allowed) ------------
__device__ __align__(16) float g_deg [NMAX];
__device__ __align__(16) float g_dinv[NMAX];
__device__ __align__(16) float g_hs  [NMAX * HID];  // h * dinv[row]
__device__ __align__(16) float g_t   [NMAX * HID];  // accumulator (init = hs)
__device__ __align__(16) float g_in  [NMAX * HID];  // next-layer input
__device__ int g_src[EMAX];
__device__ int g_dst[EMAX];
__device__ int g_is64;

// ---------------- edge dtype detection + int32 conversion ------------------
// int64 little-endian with values < 2^31 => every odd 32-bit word is 0.
__global__ void detect_k(const int* __restrict__ w, int nwords) {
    __shared__ int any;
    if (threadIdx.x == 0) any = 0;
    __syncthreads();
    for (int i = 2 * threadIdx.x + 1; i < nwords; i += 2 * blockDim.x)
        if (w[i] != 0) any = 1;
    __syncthreads();
    if (threadIdx.x == 0) g_is64 = (any == 0) ? 1 : 0;
}

__global__ void convert_k(const int* __restrict__ w, int E) {
    int i = blockIdx.x * blockDim.x + threadIdx.x;
    if (i >= E) return;
    if (g_is64) {
        g_src[i] = w[2 * i];
        g_dst[i] = w[2 * (E + i)];
    } else {
        g_src[i] = w[i];
        g_dst[i] = w[E + i];
    }
}

// ---------------- degree / dinv --------------------------------------------
__global__ void deg_init_k(int N) {
    int i = blockIdx.x * blockDim.x + threadIdx.x;
    if (i < N) g_deg[i] = 1.0f;                  // self-loop
}
__global__ void deg_scatter_k(int E) {
    int e = blockIdx.x * blockDim.x + threadIdx.x;
    if (e < E) atomicAdd(&g_deg[g_dst[e]], 1.0f);
}
__global__ void dinv_k(int N) {
    int i = blockIdx.x * blockDim.x + threadIdx.x;
    if (i < N) g_dinv[i] = rsqrtf(g_deg[i]);
}

// ---------------- tiled fp32 GEMM with fused dinv-scale epilogue -----------
// C[M,HID] = A[M,K] @ B[K,HID];  writes  g_hs = C*dinv[row],  g_t = same.
// A_ext == nullptr  ->  A = g_in (device symbol referenced in device code).
#define BM 64
#define BN 64
#define BK 16
__global__ __launch_bounds__(256) void gemm_fused_k(
        const float* __restrict__ A_ext, const float* __restrict__ B,
        int M, int K) {
    const float* __restrict__ A = A_ext ? A_ext : (const float*)g_in;
    __shared__ float As[BM][BK + 1];
    __shared__ float Bs[BK][BN + 1];
    const int tx = threadIdx.x, ty = threadIdx.y;
    const int tid = ty * 16 + tx;
    const int row0 = blockIdx.y * BM;
    const int col0 = blockIdx.x * BN;
    float acc[4][4] = {};
    for (int k0 = 0; k0 < K; k0 += BK) {
        for (int i = tid; i < BM * BK; i += 256) {
            int r = i / BK, c = i % BK;
            int gr = row0 + r, gc = k0 + c;
            As[r][c] = (gr < M && gc < K) ? A[(long long)gr * K + gc] : 0.0f;
        }
        for (int i = tid; i < BK * BN; i += 256) {
            int r = i / BN, c = i % BN;
            int gr = k0 + r, gc = col0 + c;
            Bs[r][c] = (gr < K && gc < HID) ? B[(long long)gr * HID + gc] : 0.0f;
        }
        __syncthreads();
        #pragma unroll
        for (int kk = 0; kk < BK; kk++) {
            float a[4], b[4];
            #pragma unroll
            for (int i = 0; i < 4; i++) a[i] = As[ty * 4 + i][kk];
            #pragma unroll
            for (int j = 0; j < 4; j++) b[j] = Bs[kk][tx * 4 + j];
            #pragma unroll
            for (int i = 0; i < 4; i++)
                #pragma unroll
                for (int j = 0; j < 4; j++) acc[i][j] = fmaf(a[i], b[j], acc[i][j]);
        }
        __syncthreads();
    }
    #pragma unroll
    for (int i = 0; i < 4; i++) {
        int gr = row0 + ty * 4 + i;
        if (gr >= M) continue;
        float dv = g_dinv[gr];
        #pragma unroll
        for (int j = 0; j < 4; j++) {
            int gc = col0 + tx * 4 + j;
            if (gc < HID) {
                long long off = (long long)gr * HID + gc;
                float v = acc[i][j] * dv;
                g_hs[off] = v;
                g_t [off] = v;
            }
        }
    }
}

// ---------------- edge scatter: t[dst] += hs[src]  (float2 atomics) --------
__global__ void scatter_k(int E) {
    int gtid   = blockIdx.x * blockDim.x + threadIdx.x;
    int warp   = gtid >> 5;
    int lane   = gtid & 31;
    int nwarps = (gridDim.x * blockDim.x) >> 5;
    const int HID2 = HID / 2;                    // 123 float2 per row
    for (int e = warp; e < E; e += nwarps) {
        int s = g_src[e];
        int d = g_dst[e];
        const float2* hs = (const float2*)(g_hs + (long long)s * HID);
        float2*       t  = (float2*)      (g_t  + (long long)d * HID);
        for (int c = lane; c < HID2; c += 32)
            atomicAdd(t + c, hs[c]);
    }
}

// ---------------- epilogue: g_in = relu(dinv[row]*t + b) -------------------
__global__ void bias_relu_k(const float* __restrict__ b, int total) {
    int i = blockIdx.x * blockDim.x + threadIdx.x;
    if (i >= total) return;
    int n = i / HID, c = i - n * HID;
    float v = g_dinv[n] * g_t[i] + b[c];
    g_in[i] = v > 0.0f ? v : 0.0f;
}

// ---------------- final: v = dinv*t + b, row log_softmax -> out ------------
__global__ void logsoftmax_k(const float* __restrict__ b, float* __restrict__ out) {
    int n = blockIdx.x;
    int c = threadIdx.x;                          // blockDim = 256
    float dinv = g_dinv[n];
    const float* t = g_t + (long long)n * HID;
    float myv = 0.0f;
    float val = -INFINITY;
    if (c < HID) { myv = dinv * t[c] + b[c]; val = myv; }

    __shared__ float red[8];
    float m = val;
    #pragma unroll
    for (int o = 16; o > 0; o >>= 1) m = fmaxf(m, __shfl_down_sync(0xffffffffu, m, o));
    if ((threadIdx.x & 31) == 0) red[threadIdx.x >> 5] = m;
    __syncthreads();
    if (threadIdx.x < 32) {
        float mm = (threadIdx.x < 8) ? red[threadIdx.x] : -INFINITY;
        #pragma unroll
        for (int o = 4; o > 0; o >>= 1) mm = fmaxf(mm, __shfl_down_sync(0xffffffffu, mm, o));
        if (threadIdx.x == 0) red[0] = mm;
    }
    __syncthreads();
    float mx = red[0];
    __syncthreads();

    float ex = (c < HID) ? expf(myv - mx) : 0.0f;
    float s = ex;
    #pragma unroll
    for (int o = 16; o > 0; o >>= 1) s += __shfl_down_sync(0xffffffffu, s, o);
    if ((threadIdx.x & 31) == 0) red[threadIdx.x >> 5] = s;
    __syncthreads();
    if (threadIdx.x < 32) {
        float ss = (threadIdx.x < 8) ? red[threadIdx.x] : 0.0f;
        #pragma unroll
        for (int o = 4; o > 0; o >>= 1) ss += __shfl_down_sync(0xffffffffu, ss, o);
        if (threadIdx.x == 0) red[0] = ss;
    }
    __syncthreads();
    float lse = logf(red[0]);
    if (c < HID) out[(long long)n * HID + c] = myv - mx - lse;
}

// ---------------- launch ----------------------------------------------------
extern "C" void kernel_launch(void* const* d_in, const int* in_sizes, int n_in,
                              void* d_out, int out_size) {
    const float* x  = (const float*)d_in[0];
    const int*   ei = (const int*)  d_in[1];
    const float* W1 = (const float*)d_in[2];
    const float* b1 = (const float*)d_in[3];
    const float* W2 = (const float*)d_in[4];
    const float* b2 = (const float*)d_in[5];
    const float* W3 = (const float*)d_in[6];
    const float* b3 = (const float*)d_in[7];
    const float* W4 = (const float*)d_in[8];
    const float* b4 = (const float*)d_in[9];
    float* out = (float*)d_out;

    const int HIDc = in_sizes[3];                 // 246
    const int F_IN = in_sizes[2] / HIDc;          // 256
    const int N    = in_sizes[0] / F_IN;          // 50000
    const int E    = in_sizes[1] / 2;             // 320000 (elem count / 2, any dtype)
    const int total = N * HIDc;

    // dtype detection + int32 conversion of the edge list
    int nwords = (2 * E < 4096) ? 2 * E : 4096;
    detect_k<<<1, 256>>>(ei, nwords);
    convert_k<<<(E + 255) / 256, 256>>>(ei, E);

    // degrees + dinv
    deg_init_k<<<(N + 255) / 256, 256>>>(N);
    deg_scatter_k<<<(E + 255) / 256, 256>>>(E);
    dinv_k<<<(N + 255) / 256, 256>>>(N);

    dim3 gblk(16, 16);
    dim3 ggrid((HIDc + BN - 1) / BN, (N + BM - 1) / BM);
    const int eb = 256;
    const int eg = (E * 32 + eb - 1) / eb;        // one warp per edge
    const int tb = 256;
    const int tg = (total + tb - 1) / tb;

    const float* Ws[4] = {W1, W2, W3, W4};
    const float* bs[4] = {b1, b2, b3, b4};

    for (int layer = 0; layer < 4; layer++) {
        if (layer == 0)
            gemm_fused_k<<<ggrid, gblk>>>(x, Ws[0], N, F_IN);
        else
            gemm_fused_k<<<ggrid, gblk>>>(nullptr, Ws[layer], N, HIDc);
        scatter_k<<<eg, eb>>>(E);
        if (layer < 3)
            bias_relu_k<<<tg, tb>>>(bs[layer], total);
        else
            logsoftmax_k<<<N, 256>>>(bs[3], out);
    }
    (void)n_in; (void)out_size;
}

// round 3
// speedup vs baseline: 1.5612x; 1.5612x over previous
#include <cuda_runtime.h>
#include <math.h>

#define HID   246
#define NMAX  50000
#define EMAX  320000
#define NBLK  ((NMAX + 255) / 256)      // 196 scan blocks

// ---------------- device-global scratch (no allocation allowed) ------------
__device__ __align__(16) float g_dinv[NMAX];
__device__ __align__(16) float g_hs  [NMAX * HID];  // h * dinv[row] (GEMM out)
__device__ __align__(16) float g_in  [NMAX * HID];  // next-layer input
__device__ int g_src[EMAX];
__device__ int g_dst[EMAX];
__device__ int g_cnt[NMAX];            // in-degree (edges only)
__device__ int g_rsI[NMAX];            // inclusive scan scratch
__device__ int g_rowstart[NMAX];
__device__ int g_cursor[NMAX];
__device__ int g_csr[EMAX];            // src lists grouped by dst
__device__ int g_bsum[NBLK];
__device__ int g_boff[NBLK];
__device__ int g_is64;

// ---------------- edge dtype detection + conversion + counting -------------
__global__ void detect_k(const int* __restrict__ w, int nwords) {
    __shared__ int any;
    if (threadIdx.x == 0) any = 0;
    __syncthreads();
    for (int i = 2 * threadIdx.x + 1; i < nwords; i += 2 * blockDim.x)
        if (w[i] != 0) any = 1;
    __syncthreads();
    if (threadIdx.x == 0) g_is64 = (any == 0) ? 1 : 0;
}

__global__ void zero_cnt_k(int N) {
    int i = blockIdx.x * blockDim.x + threadIdx.x;
    if (i < N) g_cnt[i] = 0;
}

__global__ void convert_count_k(const int* __restrict__ w, int E) {
    int i = blockIdx.x * blockDim.x + threadIdx.x;
    if (i >= E) return;
    int s, d;
    if (g_is64) { s = w[2 * i]; d = w[2 * (E + i)]; }
    else        { s = w[i];     d = w[E + i]; }
    g_src[i] = s;
    g_dst[i] = d;
    atomicAdd(&g_cnt[d], 1);
}

__global__ void dinv_k(int N) {
    int i = blockIdx.x * blockDim.x + threadIdx.x;
    if (i < N) g_dinv[i] = rsqrtf((float)(g_cnt[i] + 1));   // +1 self loop
}

// ---------------- 2-level exclusive scan of g_cnt -> g_rowstart ------------
__global__ void scan1_k(int N) {
    __shared__ int sh[256];
    int i = blockIdx.x * 256 + threadIdx.x;
    int v = (i < N) ? g_cnt[i] : 0;
    sh[threadIdx.x] = v;
    __syncthreads();
    for (int o = 1; o < 256; o <<= 1) {
        int t = (threadIdx.x >= o) ? sh[threadIdx.x - o] : 0;
        __syncthreads();
        sh[threadIdx.x] += t;
        __syncthreads();
    }
    if (i < N) g_rsI[i] = sh[threadIdx.x];
    if (threadIdx.x == 255) g_bsum[blockIdx.x] = sh[255];
}
__global__ void scan2_k(int NB) {           // single block, NB <= 256
    __shared__ int sh[256];
    int v = (threadIdx.x < NB) ? g_bsum[threadIdx.x] : 0;
    sh[threadIdx.x] = v;
    __syncthreads();
    for (int o = 1; o < 256; o <<= 1) {
        int t = (threadIdx.x >= o) ? sh[threadIdx.x - o] : 0;
        __syncthreads();
        sh[threadIdx.x] += t;
        __syncthreads();
    }
    if (threadIdx.x < NB) g_boff[threadIdx.x] = sh[threadIdx.x] - v;  // exclusive
}
__global__ void scan3_k(int N) {
    int i = blockIdx.x * blockDim.x + threadIdx.x;
    if (i >= N) return;
    int ex = g_rsI[i] - g_cnt[i] + g_boff[i >> 8];
    g_rowstart[i] = ex;
    g_cursor[i]   = ex;
}
__global__ void fill_csr_k(int E) {
    int e = blockIdx.x * blockDim.x + threadIdx.x;
    if (e >= E) return;
    int d = g_dst[e];
    int pos = atomicAdd(&g_cursor[d], 1);
    g_csr[pos] = g_src[e];
}

// ---------------- GEMM: g_hs[M,HID] = (A @ B) * dinv[row] ------------------
// A_ext == nullptr -> A = g_in.  128x64 tile, BK=16, 256 threads, 8x4/thread.
#define BM 128
#define BN 64
#define BK 16
__global__ __launch_bounds__(256, 2) void gemm_fused_k(
        const float* __restrict__ A_ext, const float* __restrict__ B,
        int M, int K, int HIDc) {
    const float* __restrict__ A = A_ext ? A_ext : (const float*)g_in;
    __shared__ float As[BK][BM + 4];    // k-major; +4 keeps float4 alignment
    __shared__ float Bs[BK][BN];
    const int tid = threadIdx.x;
    const int tx = tid & 15;            // 16 col groups of 4
    const int ty = tid >> 4;            // 16 row groups of 8
    const int row0 = blockIdx.y * BM;
    const int col0 = blockIdx.x * BN;
    float acc[8][4] = {};
    for (int k0 = 0; k0 < K; k0 += BK) {
        #pragma unroll
        for (int i = tid; i < BM * BK; i += 256) {
            int r = i >> 4, c = i & 15;           // coalesced on c
            int gr = row0 + r, gc = k0 + c;
            As[c][r] = (gr < M && gc < K) ? A[(long long)gr * K + gc] : 0.0f;
        }
        #pragma unroll
        for (int i = tid; i < BK * BN; i += 256) {
            int r = i >> 6, c = i & 63;
            int gr = k0 + r, gc = col0 + c;
            Bs[r][c] = (gr < K && gc < HIDc) ? B[(long long)gr * HIDc + gc] : 0.0f;
        }
        __syncthreads();
        #pragma unroll
        for (int kk = 0; kk < BK; kk++) {
            float4 a0 = *(const float4*)&As[kk][ty * 8];
            float4 a1 = *(const float4*)&As[kk][ty * 8 + 4];
            float4 b0 = *(const float4*)&Bs[kk][tx * 4];
            float a[8] = {a0.x, a0.y, a0.z, a0.w, a1.x, a1.y, a1.z, a1.w};
            float b[4] = {b0.x, b0.y, b0.z, b0.w};
            #pragma unroll
            for (int i = 0; i < 8; i++)
                #pragma unroll
                for (int j = 0; j < 4; j++)
                    acc[i][j] = fmaf(a[i], b[j], acc[i][j]);
        }
        __syncthreads();
    }
    #pragma unroll
    for (int i = 0; i < 8; i++) {
        int gr = row0 + ty * 8 + i;
        if (gr >= M) continue;
        float dv = g_dinv[gr];
        #pragma unroll
        for (int j = 0; j < 4; j++) {
            int gc = col0 + tx * 4 + j;
            if (gc < HIDc)
                g_hs[(long long)gr * HID + gc] = acc[i][j] * dv;
        }
    }
}

// ---------------- fused gather + bias (+relu | +log_softmax) ---------------
// One block (256 threads) per node; thread c owns column c (c < HID).
__global__ __launch_bounds__(256) void gather_k(const float* __restrict__ b,
                                                int last, float* __restrict__ out) {
    const int n = blockIdx.x;
    const int c = threadIdx.x;
    const int start = g_rowstart[n];
    const int cnt   = g_cnt[n];
    float acc = 0.0f;
    if (c < HID) acc = g_hs[(long long)n * HID + c];    // self loop (pre-scaled)
    int j = 0;
    for (; j + 4 <= cnt; j += 4) {                       // MLP=4
        int s0 = g_csr[start + j];
        int s1 = g_csr[start + j + 1];
        int s2 = g_csr[start + j + 2];
        int s3 = g_csr[start + j + 3];
        if (c < HID) {
            float v0 = g_hs[(long long)s0 * HID + c];
            float v1 = g_hs[(long long)s1 * HID + c];
            float v2 = g_hs[(long long)s2 * HID + c];
            float v3 = g_hs[(long long)s3 * HID + c];
            acc += (v0 + v1) + (v2 + v3);
        }
    }
    for (; j < cnt; j++) {
        int s = g_csr[start + j];
        if (c < HID) acc += g_hs[(long long)s * HID + c];
    }
    float myv = 0.0f;
    if (c < HID) myv = g_dinv[n] * acc + b[c];

    if (!last) {
        if (c < HID) g_in[(long long)n * HID + c] = myv > 0.0f ? myv : 0.0f;
        return;
    }
    // fused log_softmax over the row
    __shared__ float red[8];
    float val = (c < HID) ? myv : -INFINITY;
    float m = val;
    #pragma unroll
    for (int o = 16; o > 0; o >>= 1) m = fmaxf(m, __shfl_down_sync(0xffffffffu, m, o));
    if ((c & 31) == 0) red[c >> 5] = m;
    __syncthreads();
    if (c < 32) {
        float mm = (c < 8) ? red[c] : -INFINITY;
        #pragma unroll
        for (int o = 4; o > 0; o >>= 1) mm = fmaxf(mm, __shfl_down_sync(0xffffffffu, mm, o));
        if (c == 0) red[0] = mm;
    }
    __syncthreads();
    float mx = red[0];
    __syncthreads();
    float ex = (c < HID) ? expf(myv - mx) : 0.0f;
    float s = ex;
    #pragma unroll
    for (int o = 16; o > 0; o >>= 1) s += __shfl_down_sync(0xffffffffu, s, o);
    if ((c & 31) == 0) red[c >> 5] = s;
    __syncthreads();
    if (c < 32) {
        float ss = (c < 8) ? red[c] : 0.0f;
        #pragma unroll
        for (int o = 4; o > 0; o >>= 1) ss += __shfl_down_sync(0xffffffffu, ss, o);
        if (c == 0) red[0] = ss;
    }
    __syncthreads();
    float lse = logf(red[0]);
    if (c < HID) out[(long long)n * HID + c] = myv - mx - lse;
}

// ---------------- launch ----------------------------------------------------
extern "C" void kernel_launch(void* const* d_in, const int* in_sizes, int n_in,
                              void* d_out, int out_size) {
    const float* x  = (const float*)d_in[0];
    const int*   ei = (const int*)  d_in[1];
    const float* W1 = (const float*)d_in[2];
    const float* b1 = (const float*)d_in[3];
    const float* W2 = (const float*)d_in[4];
    const float* b2 = (const float*)d_in[5];
    const float* W3 = (const float*)d_in[6];
    const float* b3 = (const float*)d_in[7];
    const float* W4 = (const float*)d_in[8];
    const float* b4 = (const float*)d_in[9];
    float* out = (float*)d_out;

    const int HIDc = in_sizes[3];                 // 246
    const int F_IN = in_sizes[2] / HIDc;          // 256
    const int N    = in_sizes[0] / F_IN;          // 50000
    const int E    = in_sizes[1] / 2;             // 320000

    // edge preprocessing -> CSR (grouped by dst)
    int nwords = (2 * E < 4096) ? 2 * E : 4096;
    detect_k<<<1, 256>>>(ei, nwords);
    zero_cnt_k<<<(N + 255) / 256, 256>>>(N);
    convert_count_k<<<(E + 255) / 256, 256>>>(ei, E);
    dinv_k<<<(N + 255) / 256, 256>>>(N);
    int nb = (N + 255) / 256;
    scan1_k<<<nb, 256>>>(N);
    scan2_k<<<1, 256>>>(nb);
    scan3_k<<<nb, 256>>>(N);
    fill_csr_k<<<(E + 255) / 256, 256>>>(E);

    dim3 ggrid((HIDc + BN - 1) / BN, (N + BM - 1) / BM);
    const float* Ws[4] = {W1, W2, W3, W4};
    const float* bs[4] = {b1, b2, b3, b4};

    for (int layer = 0; layer < 4; layer++) {
        if (layer == 0)
            gemm_fused_k<<<ggrid, 256>>>(x, Ws[0], N, F_IN, HIDc);
        else
            gemm_fused_k<<<ggrid, 256>>>(nullptr, Ws[layer], N, HIDc, HIDc);
        gather_k<<<N, 256>>>(bs[layer], layer == 3 ? 1 : 0, out);
    }
    (void)n_in; (void)out_size;
}

// round 4
// speedup vs baseline: 2.1851x; 1.3997x over previous
#include <cuda_runtime.h>
#include <cuda_bf16.h>
#include <math.h>

#define HID   246
#define NMAX  50000
#define EMAX  320000
#define KP    256            // padded K for all layers
#define NBLK  ((NMAX + 255) / 256)

// ---------------- device-global scratch (no allocation allowed) ------------
__device__ __align__(16) float g_dinv[NMAX];
__device__ __align__(16) float g_hs  [NMAX * HID];          // (A@W)*dinv[row]
__device__ __align__(16) __nv_bfloat16 g_ahi[NMAX * KP];    // activation hi
__device__ __align__(16) __nv_bfloat16 g_alo[NMAX * KP];    // activation lo
__device__ __align__(16) __nv_bfloat16 g_whi[4 * KP * KP];  // weights hi (padded)
__device__ __align__(16) __nv_bfloat16 g_wlo[4 * KP * KP];  // weights lo
__device__ int g_src[EMAX];
__device__ int g_dst[EMAX];
__device__ int g_cnt[NMAX];
__device__ int g_rsI[NMAX];
__device__ int g_rowstart[NMAX];
__device__ int g_cursor[NMAX];
__device__ int g_csr[EMAX];
__device__ int g_bsum[NBLK];
__device__ int g_boff[NBLK];
__device__ int g_is64;

// ---------------- helpers ---------------------------------------------------
__device__ __forceinline__ void split_bf16(float v, __nv_bfloat16& hi, __nv_bfloat16& lo) {
    hi = __float2bfloat16(v);
    lo = __float2bfloat16(v - __bfloat162float(hi));
}
__device__ __forceinline__ unsigned smaddr(const void* p) {
    return (unsigned)__cvta_generic_to_shared(p);
}
__device__ __forceinline__ void ldsm_x4(unsigned a, unsigned& r0, unsigned& r1,
                                        unsigned& r2, unsigned& r3) {
    asm volatile("ldmatrix.sync.aligned.m8n8.x4.shared.b16 {%0,%1,%2,%3}, [%4];"
                 : "=r"(r0), "=r"(r1), "=r"(r2), "=r"(r3) : "r"(a));
}
__device__ __forceinline__ void ldsm_x4_t(unsigned a, unsigned& r0, unsigned& r1,
                                          unsigned& r2, unsigned& r3) {
    asm volatile("ldmatrix.sync.aligned.m8n8.x4.trans.shared.b16 {%0,%1,%2,%3}, [%4];"
                 : "=r"(r0), "=r"(r1), "=r"(r2), "=r"(r3) : "r"(a));
}
__device__ __forceinline__ void mma_bf16(float* c, const unsigned* a, unsigned b0, unsigned b1) {
    asm volatile("mma.sync.aligned.m16n8k16.row.col.f32.bf16.bf16.f32 "
                 "{%0,%1,%2,%3}, {%4,%5,%6,%7}, {%8,%9}, {%0,%1,%2,%3};"
                 : "+f"(c[0]), "+f"(c[1]), "+f"(c[2]), "+f"(c[3])
                 : "r"(a[0]), "r"(a[1]), "r"(a[2]), "r"(a[3]), "r"(b0), "r"(b1));
}

// ---------------- edge preprocessing ---------------------------------------
__global__ void detect_k(const int* __restrict__ w, int nwords) {
    __shared__ int any;
    if (threadIdx.x == 0) any = 0;
    __syncthreads();
    for (int i = 2 * threadIdx.x + 1; i < nwords; i += 2 * blockDim.x)
        if (w[i] != 0) any = 1;
    __syncthreads();
    if (threadIdx.x == 0) g_is64 = (any == 0) ? 1 : 0;
}
__global__ void zero_cnt_k(int N) {
    int i = blockIdx.x * blockDim.x + threadIdx.x;
    if (i < N) g_cnt[i] = 0;
}
__global__ void convert_count_k(const int* __restrict__ w, int E) {
    int i = blockIdx.x * blockDim.x + threadIdx.x;
    if (i >= E) return;
    int s, d;
    if (g_is64) { s = w[2 * i]; d = w[2 * (E + i)]; }
    else        { s = w[i];     d = w[E + i]; }
    g_src[i] = s;
    g_dst[i] = d;
    atomicAdd(&g_cnt[d], 1);
}
__global__ void dinv_k(int N) {
    int i = blockIdx.x * blockDim.x + threadIdx.x;
    if (i < N) g_dinv[i] = rsqrtf((float)(g_cnt[i] + 1));
}
__global__ void scan1_k(int N) {
    __shared__ int sh[256];
    int i = blockIdx.x * 256 + threadIdx.x;
    int v = (i < N) ? g_cnt[i] : 0;
    sh[threadIdx.x] = v;
    __syncthreads();
    for (int o = 1; o < 256; o <<= 1) {
        int t = (threadIdx.x >= o) ? sh[threadIdx.x - o] : 0;
        __syncthreads();
        sh[threadIdx.x] += t;
        __syncthreads();
    }
    if (i < N) g_rsI[i] = sh[threadIdx.x];
    if (threadIdx.x == 255) g_bsum[blockIdx.x] = sh[255];
}
__global__ void scan2_k(int NB) {
    __shared__ int sh[256];
    int v = (threadIdx.x < NB) ? g_bsum[threadIdx.x] : 0;
    sh[threadIdx.x] = v;
    __syncthreads();
    for (int o = 1; o < 256; o <<= 1) {
        int t = (threadIdx.x >= o) ? sh[threadIdx.x - o] : 0;
        __syncthreads();
        sh[threadIdx.x] += t;
        __syncthreads();
    }
    if (threadIdx.x < NB) g_boff[threadIdx.x] = sh[threadIdx.x] - v;
}
__global__ void scan3_k(int N) {
    int i = blockIdx.x * blockDim.x + threadIdx.x;
    if (i >= N) return;
    int ex = g_rsI[i] - g_cnt[i] + g_boff[i >> 8];
    g_rowstart[i] = ex;
    g_cursor[i]   = ex;
}
__global__ void fill_csr_k(int E) {
    int e = blockIdx.x * blockDim.x + threadIdx.x;
    if (e >= E) return;
    int d = g_dst[e];
    int pos = atomicAdd(&g_cursor[d], 1);
    g_csr[pos] = g_src[e];
}

// ---------------- conversions ----------------------------------------------
// x [N,256] fp32 -> g_ahi/g_alo
__global__ void conv_x_k(const float* __restrict__ x, int total) {
    int i = blockIdx.x * blockDim.x + threadIdx.x;
    if (i >= total) return;
    split_bf16(x[i], g_ahi[i], g_alo[i]);
}
// W [K,246] fp32 -> g_whi/g_wlo slab [256,256] zero-padded
__global__ void conv_w_k(const float* __restrict__ W, int K, int layer) {
    int i = blockIdx.x * blockDim.x + threadIdx.x;
    if (i >= KP * KP) return;
    int r = i >> 8, c = i & 255;
    float v = (r < K && c < HID) ? W[r * HID + c] : 0.0f;
    __nv_bfloat16 hi, lo;
    split_bf16(v, hi, lo);
    g_whi[layer * KP * KP + i] = hi;
    g_wlo[layer * KP * KP + i] = lo;
}

// ---------------- bf16x3 tensor-core GEMM ----------------------------------
// g_hs[M,246] = (A @ W_layer) * dinv[row], computed as A_hi*W_hi + A_hi*W_lo
// + A_lo*W_hi over K' = 3*256 = 768.  Tile 128x128, k-block 32, 8 warps.
#define BM 128
#define BN 128
#define BKB 32
__global__ __launch_bounds__(256) void gemm_tc_k(int M, int layer) {
    __shared__ __nv_bfloat16 As[BM][40];    // pad 32->40 (80B rows, 16B aligned)
    __shared__ __nv_bfloat16 Bs[BKB][136];  // pad 128->136 (272B rows)
    const int tid  = threadIdx.x;
    const int lane = tid & 31;
    const int wid  = tid >> 5;
    const int wm   = (wid & 3) * 32;        // warp tile 32 (M) x 64 (N)
    const int wn   = (wid >> 2) * 64;
    const int row0 = blockIdx.y * BM;
    const int col0 = blockIdx.x * BN;
    const __nv_bfloat16* wbase_hi = g_whi + layer * KP * KP;
    const __nv_bfloat16* wbase_lo = g_wlo + layer * KP * KP;

    float acc[2][8][4];
    #pragma unroll
    for (int a = 0; a < 2; a++)
        #pragma unroll
        for (int b = 0; b < 8; b++)
            #pragma unroll
            for (int c = 0; c < 4; c++) acc[a][b][c] = 0.0f;

    const int4 zero4 = make_int4(0, 0, 0, 0);
    #pragma unroll 1
    for (int kb = 0; kb < 24; kb++) {
        int p    = kb >> 3;                  // 0: hi*hi  1: hi*lo  2: lo*hi
        int ksrc = (kb & 7) * BKB;
        const __nv_bfloat16* Asrc = (p < 2) ? g_ahi : g_alo;
        const __nv_bfloat16* Bsrc = (p == 1) ? wbase_lo : wbase_hi;
        // load A tile: 128 rows x 32 bf16 = 512 int4
        #pragma unroll
        for (int it = 0; it < 2; it++) {
            int slot = tid + it * 256;
            int r = slot >> 2, q = slot & 3;
            int gr = row0 + r;
            int4 v = (gr < M) ? *(const int4*)(Asrc + (long long)gr * KP + ksrc + q * 8)
                              : zero4;
            *(int4*)&As[r][q * 8] = v;
        }
        // load B tile: 32 rows x 128 bf16 = 512 int4
        #pragma unroll
        for (int it = 0; it < 2; it++) {
            int slot = tid + it * 256;
            int r = slot >> 4, q = slot & 15;
            *(int4*)&Bs[r][q * 8] =
                *(const int4*)(Bsrc + (ksrc + r) * KP + col0 + q * 8);
        }
        __syncthreads();
        #pragma unroll
        for (int ks = 0; ks < 2; ks++) {
            const int kk = ks * 16;
            unsigned af[2][4], bf[4][4];
            #pragma unroll
            for (int mt = 0; mt < 2; mt++) {
                int r = wm + mt * 16 + (lane & 7) + (lane & 8);
                int c = kk + ((lane & 16) ? 8 : 0);
                ldsm_x4(smaddr(&As[r][c]), af[mt][0], af[mt][1], af[mt][2], af[mt][3]);
            }
            #pragma unroll
            for (int nt = 0; nt < 4; nt++) {
                int r = kk + (lane & 7) + (lane & 8);
                int c = wn + nt * 16 + ((lane & 16) ? 8 : 0);
                ldsm_x4_t(smaddr(&Bs[r][c]), bf[nt][0], bf[nt][1], bf[nt][2], bf[nt][3]);
            }
            #pragma unroll
            for (int mt = 0; mt < 2; mt++)
                #pragma unroll
                for (int j = 0; j < 8; j++)
                    mma_bf16(acc[mt][j], af[mt], bf[j >> 1][(j & 1) * 2],
                             bf[j >> 1][(j & 1) * 2 + 1]);
        }
        __syncthreads();
    }
    // epilogue: scale by dinv[row], store fp32 g_hs with bounds
    const int gID = lane >> 2, tig = lane & 3;
    #pragma unroll
    for (int mt = 0; mt < 2; mt++) {
        #pragma unroll
        for (int half = 0; half < 2; half++) {
            int gr = row0 + wm + mt * 16 + gID + half * 8;
            if (gr >= M) continue;
            float dv = g_dinv[gr];
            #pragma unroll
            for (int j = 0; j < 8; j++) {
                int gc = col0 + wn + j * 8 + tig * 2;
                float v0 = acc[mt][j][half * 2 + 0] * dv;
                float v1 = acc[mt][j][half * 2 + 1] * dv;
                if (gc + 1 < HID) {
                    *(float2*)&g_hs[(long long)gr * HID + gc] = make_float2(v0, v1);
                } else if (gc < HID) {
                    g_hs[(long long)gr * HID + gc] = v0;
                }
            }
        }
    }
}

// ---------------- fused gather + bias (+relu+split | +log_softmax) ---------
__global__ __launch_bounds__(256) void gather_k(const float* __restrict__ b,
                                                int last, float* __restrict__ out) {
    const int n = blockIdx.x;
    const int c = threadIdx.x;
    const int start = g_rowstart[n];
    const int cnt   = g_cnt[n];
    float acc = 0.0f;
    if (c < HID) acc = g_hs[(long long)n * HID + c];    // self loop (pre-scaled)
    int j = 0;
    for (; j + 4 <= cnt; j += 4) {
        int s0 = g_csr[start + j];
        int s1 = g_csr[start + j + 1];
        int s2 = g_csr[start + j + 2];
        int s3 = g_csr[start + j + 3];
        if (c < HID) {
            float v0 = g_hs[(long long)s0 * HID + c];
            float v1 = g_hs[(long long)s1 * HID + c];
            float v2 = g_hs[(long long)s2 * HID + c];
            float v3 = g_hs[(long long)s3 * HID + c];
            acc += (v0 + v1) + (v2 + v3);
        }
    }
    for (; j < cnt; j++) {
        int s = g_csr[start + j];
        if (c < HID) acc += g_hs[(long long)s * HID + c];
    }
    float myv = 0.0f;
    if (c < HID) myv = g_dinv[n] * acc + b[c];

    if (!last) {
        long long off = (long long)n * KP + c;
        if (c < HID) {
            float v = myv > 0.0f ? myv : 0.0f;
            split_bf16(v, g_ahi[off], g_alo[off]);
        } else {                                        // zero K-padding cols
            g_ahi[off] = __float2bfloat16(0.0f);
            g_alo[off] = __float2bfloat16(0.0f);
        }
        return;
    }
    // fused log_softmax
    __shared__ float red[8];
    float val = (c < HID) ? myv : -INFINITY;
    float m = val;
    #pragma unroll
    for (int o = 16; o > 0; o >>= 1) m = fmaxf(m, __shfl_down_sync(0xffffffffu, m, o));
    if ((c & 31) == 0) red[c >> 5] = m;
    __syncthreads();
    if (c < 32) {
        float mm = (c < 8) ? red[c] : -INFINITY;
        #pragma unroll
        for (int o = 4; o > 0; o >>= 1) mm = fmaxf(mm, __shfl_down_sync(0xffffffffu, mm, o));
        if (c == 0) red[0] = mm;
    }
    __syncthreads();
    float mx = red[0];
    __syncthreads();
    float ex = (c < HID) ? expf(myv - mx) : 0.0f;
    float s = ex;
    #pragma unroll
    for (int o = 16; o > 0; o >>= 1) s += __shfl_down_sync(0xffffffffu, s, o);
    if ((c & 31) == 0) red[c >> 5] = s;
    __syncthreads();
    if (c < 32) {
        float ss = (c < 8) ? red[c] : 0.0f;
        #pragma unroll
        for (int o = 4; o > 0; o >>= 1) ss += __shfl_down_sync(0xffffffffu, ss, o);
        if (c == 0) red[0] = ss;
    }
    __syncthreads();
    float lse = logf(red[0]);
    if (c < HID) out[(long long)n * HID + c] = myv - mx - lse;
}

// ---------------- launch ----------------------------------------------------
extern "C" void kernel_launch(void* const* d_in, const int* in_sizes, int n_in,
                              void* d_out, int out_size) {
    const float* x  = (const float*)d_in[0];
    const int*   ei = (const int*)  d_in[1];
    const float* W1 = (const float*)d_in[2];
    const float* b1 = (const float*)d_in[3];
    const float* W2 = (const float*)d_in[4];
    const float* b2 = (const float*)d_in[5];
    const float* W3 = (const float*)d_in[6];
    const float* b3 = (const float*)d_in[7];
    const float* W4 = (const float*)d_in[8];
    const float* b4 = (const float*)d_in[9];
    float* out = (float*)d_out;

    const int HIDc = in_sizes[3];                 // 246
    const int F_IN = in_sizes[2] / HIDc;          // 256
    const int N    = in_sizes[0] / F_IN;          // 50000
    const int E    = in_sizes[1] / 2;             // 320000

    // edge preprocessing -> CSR
    int nwords = (2 * E < 4096) ? 2 * E : 4096;
    detect_k<<<1, 256>>>(ei, nwords);
    zero_cnt_k<<<(N + 255) / 256, 256>>>(N);
    convert_count_k<<<(E + 255) / 256, 256>>>(ei, E);
    dinv_k<<<(N + 255) / 256, 256>>>(N);
    int nb = (N + 255) / 256;
    scan1_k<<<nb, 256>>>(N);
    scan2_k<<<1, 256>>>(nb);
    scan3_k<<<nb, 256>>>(N);
    fill_csr_k<<<(E + 255) / 256, 256>>>(E);

    // conversions
    conv_x_k<<<(N * F_IN + 255) / 256, 256>>>(x, N * F_IN);
    conv_w_k<<<(KP * KP + 255) / 256, 256>>>(W1, F_IN, 0);
    conv_w_k<<<(KP * KP + 255) / 256, 256>>>(W2, HIDc, 1);
    conv_w_k<<<(KP * KP + 255) / 256, 256>>>(W3, HIDc, 2);
    conv_w_k<<<(KP * KP + 255) / 256, 256>>>(W4, HIDc, 3);

    dim3 ggrid((HIDc + BN - 1) / BN, (N + BM - 1) / BM);   // (2, 391)
    const float* bs[4] = {b1, b2, b3, b4};

    for (int layer = 0; layer < 4; layer++) {
        gemm_tc_k<<<ggrid, 256>>>(N, layer);
        gather_k<<<N, 256>>>(bs[layer], layer == 3 ? 1 : 0, out);
    }
    (void)n_in; (void)out_size;
}

// round 6
// speedup vs baseline: 3.1622x; 1.4471x over previous
#include <cuda_runtime.h>
#include <cuda_bf16.h>
#include <math.h>
#include <stdint.h>

#define HID   246
#define NMAX  50000
#define EMAX  320000
#define KP    256            // padded K (activation row stride)
#define HSP   256            // padded g_hs row stride (floats)
#define NBLK  ((NMAX + 255) / 256)

// ---------------- device-global scratch (no allocation allowed) ------------
__device__ __align__(16) float g_dinv[NMAX];
__device__ __align__(16) float g_hs  [NMAX * HSP];          // (A@W)*dinv, padded
__device__ __align__(16) __nv_bfloat16 g_ahi[NMAX * KP];    // activation hi
__device__ __align__(16) __nv_bfloat16 g_alo[NMAX * KP];    // activation lo
__device__ __align__(16) __nv_bfloat16 g_whi[4 * KP * KP];  // W hi [k][n] padded
__device__ __align__(16) __nv_bfloat16 g_wlo[4 * KP * KP];  // W lo
__device__ __align__(16) float g_bpad[4 * HSP];             // padded biases
__device__ int g_src[EMAX];
__device__ int g_dst[EMAX];
__device__ int g_cnt[NMAX];
__device__ int g_rsI[NMAX];
__device__ int g_rowstart[NMAX];
__device__ int g_cursor[NMAX];
__device__ int g_csr[EMAX];
__device__ int g_bsum[NBLK];
__device__ int g_boff[NBLK];
__device__ int g_is64;

// ---------------- helpers ---------------------------------------------------
__device__ __forceinline__ void split_bf16(float v, __nv_bfloat16& hi, __nv_bfloat16& lo) {
    hi = __float2bfloat16(v);
    lo = __float2bfloat16(v - __bfloat162float(hi));
}
__device__ __forceinline__ unsigned smaddr(const void* p) {
    return (unsigned)__cvta_generic_to_shared(p);
}
__device__ __forceinline__ void ldsm_x4(unsigned a, unsigned& r0, unsigned& r1,
                                        unsigned& r2, unsigned& r3) {
    asm volatile("ldmatrix.sync.aligned.m8n8.x4.shared.b16 {%0,%1,%2,%3}, [%4];"
                 : "=r"(r0), "=r"(r1), "=r"(r2), "=r"(r3) : "r"(a));
}
__device__ __forceinline__ void ldsm_x4_t(unsigned a, unsigned& r0, unsigned& r1,
                                          unsigned& r2, unsigned& r3) {
    asm volatile("ldmatrix.sync.aligned.m8n8.x4.trans.shared.b16 {%0,%1,%2,%3}, [%4];"
                 : "=r"(r0), "=r"(r1), "=r"(r2), "=r"(r3) : "r"(a));
}
__device__ __forceinline__ void mma_bf16(float* c, const unsigned* a, unsigned b0, unsigned b1) {
    asm volatile("mma.sync.aligned.m16n8k16.row.col.f32.bf16.bf16.f32 "
                 "{%0,%1,%2,%3}, {%4,%5,%6,%7}, {%8,%9}, {%0,%1,%2,%3};"
                 : "+f"(c[0]), "+f"(c[1]), "+f"(c[2]), "+f"(c[3])
                 : "r"(a[0]), "r"(a[1]), "r"(a[2]), "r"(a[3]), "r"(b0), "r"(b1));
}
__device__ __forceinline__ void cpa16(unsigned dst, const void* src) {
    asm volatile("cp.async.cg.shared.global [%0], [%1], 16;" :: "r"(dst), "l"(src));
}
__device__ __forceinline__ void cpa16z(unsigned dst, const void* src, int srcbytes) {
    asm volatile("cp.async.cg.shared.global [%0], [%1], 16, %2;"
                 :: "r"(dst), "l"(src), "r"(srcbytes));
}
#define CPA_COMMIT() asm volatile("cp.async.commit_group;" ::: "memory")

// ---------------- edge preprocessing ---------------------------------------
__global__ void detect_k(const int* __restrict__ w, int nwords) {
    __shared__ int any;
    if (threadIdx.x == 0) any = 0;
    __syncthreads();
    for (int i = 2 * threadIdx.x + 1; i < nwords; i += 2 * blockDim.x)
        if (w[i] != 0) any = 1;
    __syncthreads();
    if (threadIdx.x == 0) g_is64 = (any == 0) ? 1 : 0;
}
__global__ void zero_cnt_k(int N) {
    int i = blockIdx.x * blockDim.x + threadIdx.x;
    if (i < N) g_cnt[i] = 0;
}
__global__ void convert_count_k(const int* __restrict__ w, int E) {
    int i = blockIdx.x * blockDim.x + threadIdx.x;
    if (i >= E) return;
    int s, d;
    if (g_is64) { s = w[2 * i]; d = w[2 * (E + i)]; }
    else        { s = w[i];     d = w[E + i]; }
    g_src[i] = s;
    g_dst[i] = d;
    atomicAdd(&g_cnt[d], 1);
}
__global__ void dinv_k(int N) {
    int i = blockIdx.x * blockDim.x + threadIdx.x;
    if (i < N) g_dinv[i] = rsqrtf((float)(g_cnt[i] + 1));
}
__global__ void scan1_k(int N) {
    __shared__ int sh[256];
    int i = blockIdx.x * 256 + threadIdx.x;
    int v = (i < N) ? g_cnt[i] : 0;
    sh[threadIdx.x] = v;
    __syncthreads();
    for (int o = 1; o < 256; o <<= 1) {
        int t = (threadIdx.x >= o) ? sh[threadIdx.x - o] : 0;
        __syncthreads();
        sh[threadIdx.x] += t;
        __syncthreads();
    }
    if (i < N) g_rsI[i] = sh[threadIdx.x];
    if (threadIdx.x == 255) g_bsum[blockIdx.x] = sh[255];
}
__global__ void scan2_k(int NB) {
    __shared__ int sh[256];
    int v = (threadIdx.x < NB) ? g_bsum[threadIdx.x] : 0;
    sh[threadIdx.x] = v;
    __syncthreads();
    for (int o = 1; o < 256; o <<= 1) {
        int t = (threadIdx.x >= o) ? sh[threadIdx.x - o] : 0;
        __syncthreads();
        sh[threadIdx.x] += t;
        __syncthreads();
    }
    if (threadIdx.x < NB) g_boff[threadIdx.x] = sh[threadIdx.x] - v;
}
__global__ void scan3_k(int N) {
    int i = blockIdx.x * blockDim.x + threadIdx.x;
    if (i >= N) return;
    int ex = g_rsI[i] - g_cnt[i] + g_boff[i >> 8];
    g_rowstart[i] = ex;
    g_cursor[i]   = ex;
}
__global__ void fill_csr_k(int E) {
    int e = blockIdx.x * blockDim.x + threadIdx.x;
    if (e >= E) return;
    int d = g_dst[e];
    int pos = atomicAdd(&g_cursor[d], 1);
    g_csr[pos] = g_src[e];
}

// ---------------- conversions ----------------------------------------------
__global__ void conv_x_k(const float* __restrict__ x, int total) {
    int i = blockIdx.x * blockDim.x + threadIdx.x;
    if (i >= total) return;
    split_bf16(x[i], g_ahi[i], g_alo[i]);
}
// W [K,246] fp32 -> padded slab [256 k][256 n], split hi/lo
__global__ void conv_w_k(const float* __restrict__ W, int K, int layer) {
    int i = blockIdx.x * blockDim.x + threadIdx.x;
    if (i >= KP * KP) return;
    int r = i >> 8, c = i & 255;
    float v = (r < K && c < HID) ? W[r * HID + c] : 0.0f;
    __nv_bfloat16 hi, lo;
    split_bf16(v, hi, lo);
    g_whi[layer * KP * KP + i] = hi;
    g_wlo[layer * KP * KP + i] = lo;
}
__global__ void pad_b_k(const float* __restrict__ b, int layer) {
    int c = threadIdx.x;
    g_bpad[layer * HSP + c] = (c < HID) ? b[c] : 0.0f;
}

// ---------------- bf16x3 tensor-core GEMM (mma.sync + cp.async) ------------
// g_hs[row][0..255] = (A @ W) * dinv[row]; K' = 3*256 = 768, chunks of 32.
// Tile 128x128, 8 warps (4 M x 2 N), warp tile 32x64.  2-stage cp.async pipe.
#define BM 128
#define BN 128
#define BKB 32
#define NCHUNK 24
__global__ __launch_bounds__(256, 2) void gemm_tc_k(int M, int layer) {
    __shared__ __nv_bfloat16 As[2][BM][40];     // pad 32->40
    __shared__ __nv_bfloat16 Bs[2][BKB][136];   // pad 128->136
    const int tid  = threadIdx.x;
    const int lane = tid & 31;
    const int wid  = tid >> 5;
    const int wm   = (wid & 3) * 32;
    const int wn   = (wid >> 2) * 64;
    const int row0 = blockIdx.y * BM;
    const int col0 = blockIdx.x * BN;
    const __nv_bfloat16* wbase_hi = g_whi + layer * KP * KP;
    const __nv_bfloat16* wbase_lo = g_wlo + layer * KP * KP;

    // per-thread load slots
    const int ar0 = tid >> 2,  aq0 = tid & 3;          // A slot 0
    const int ar1 = (tid + 256) >> 2, aq1 = tid & 3;   // A slot 1 (ar0+64)
    const int br0 = tid >> 4,  bq0 = tid & 15;
    const int br1 = (tid + 256) >> 4, bq1 = tid & 15;  // br0+16

    float acc[2][8][4];
    #pragma unroll
    for (int a = 0; a < 2; a++)
        #pragma unroll
        for (int b = 0; b < 8; b++)
            #pragma unroll
            for (int c = 0; c < 4; c++) acc[a][b][c] = 0.0f;

    auto issue = [&](int chunk, int buf) {
        const int p    = chunk >> 3;                   // 0 hi*hi, 1 hi*lo, 2 lo*hi
        const int ksrc = (chunk & 7) * BKB;
        const __nv_bfloat16* Asrc = (p < 2) ? g_ahi : g_alo;
        const __nv_bfloat16* Bsrc = (p == 1) ? wbase_lo : wbase_hi;
        int gr0 = row0 + ar0, gr1 = row0 + ar1;
        cpa16z(smaddr(&As[buf][ar0][aq0 * 8]),
               Asrc + (size_t)gr0 * KP + ksrc + aq0 * 8, gr0 < M ? 16 : 0);
        cpa16z(smaddr(&As[buf][ar1][aq1 * 8]),
               Asrc + (size_t)gr1 * KP + ksrc + aq1 * 8, gr1 < M ? 16 : 0);
        cpa16(smaddr(&Bs[buf][br0][bq0 * 8]),
              Bsrc + (size_t)(ksrc + br0) * KP + col0 + bq0 * 8);
        cpa16(smaddr(&Bs[buf][br1][bq1 * 8]),
              Bsrc + (size_t)(ksrc + br1) * KP + col0 + bq1 * 8);
        CPA_COMMIT();
    };

    issue(0, 0);
    #pragma unroll 1
    for (int c = 0; c < NCHUNK; c++) {
        const int buf = c & 1;
        if (c + 1 < NCHUNK) {
            issue(c + 1, buf ^ 1);
            asm volatile("cp.async.wait_group 1;" ::: "memory");
        } else {
            asm volatile("cp.async.wait_group 0;" ::: "memory");
        }
        __syncthreads();
        #pragma unroll
        for (int ks = 0; ks < 2; ks++) {
            const int kk = ks * 16;
            unsigned af[2][4], bf[4][4];
            #pragma unroll
            for (int mt = 0; mt < 2; mt++) {
                int r = wm + mt * 16 + (lane & 7) + (lane & 8);
                int cc = kk + ((lane & 16) ? 8 : 0);
                ldsm_x4(smaddr(&As[buf][r][cc]), af[mt][0], af[mt][1], af[mt][2], af[mt][3]);
            }
            #pragma unroll
            for (int nt = 0; nt < 4; nt++) {
                int r = kk + (lane & 7) + (lane & 8);
                int cc = wn + nt * 16 + ((lane & 16) ? 8 : 0);
                ldsm_x4_t(smaddr(&Bs[buf][r][cc]), bf[nt][0], bf[nt][1], bf[nt][2], bf[nt][3]);
            }
            #pragma unroll
            for (int mt = 0; mt < 2; mt++)
                #pragma unroll
                for (int j = 0; j < 8; j++)
                    mma_bf16(acc[mt][j], af[mt], bf[j >> 1][(j & 1) * 2],
                             bf[j >> 1][(j & 1) * 2 + 1]);
        }
        __syncthreads();
    }
    // epilogue: scale by dinv[row]; unconditional col stores (padded g_hs)
    const int gID = lane >> 2, tig = lane & 3;
    #pragma unroll
    for (int mt = 0; mt < 2; mt++) {
        #pragma unroll
        for (int half = 0; half < 2; half++) {
            int gr = row0 + wm + mt * 16 + gID + half * 8;
            if (gr >= M) continue;
            float dv = g_dinv[gr];
            #pragma unroll
            for (int j = 0; j < 8; j++) {
                int gc = col0 + wn + j * 8 + tig * 2;
                float2 v = make_float2(acc[mt][j][half * 2 + 0] * dv,
                                       acc[mt][j][half * 2 + 1] * dv);
                *(float2*)&g_hs[(size_t)gr * HSP + gc] = v;
            }
        }
    }
}

// ---------------- fused gather + bias (+relu+split | +log_softmax) ---------
// 4 nodes/block, 64 threads/node, float4 per thread.
union BfPack { __nv_bfloat16 h[4]; uint2 u; };

__global__ __launch_bounds__(256) void gather_k(int last, int layer,
                                                float* __restrict__ out, int N) {
    const int g = threadIdx.x >> 6;
    const int t = threadIdx.x & 63;
    const int lane = threadIdx.x & 31;
    const int wig = (threadIdx.x >> 5) & 1;
    const int n = blockIdx.x * 4 + g;
    if (n >= N) return;

    const float4* hs4 = (const float4*)g_hs;
    float4 acc = hs4[(size_t)n * 64 + t];               // self loop (pre-scaled)
    const int start = g_rowstart[n];
    const int cnt   = g_cnt[n];
    int j = 0;
    for (; j + 4 <= cnt; j += 4) {
        int s0 = g_csr[start + j];
        int s1 = g_csr[start + j + 1];
        int s2 = g_csr[start + j + 2];
        int s3 = g_csr[start + j + 3];
        float4 a0 = hs4[(size_t)s0 * 64 + t];
        float4 a1 = hs4[(size_t)s1 * 64 + t];
        float4 a2 = hs4[(size_t)s2 * 64 + t];
        float4 a3 = hs4[(size_t)s3 * 64 + t];
        acc.x += (a0.x + a1.x) + (a2.x + a3.x);
        acc.y += (a0.y + a1.y) + (a2.y + a3.y);
        acc.z += (a0.z + a1.z) + (a2.z + a3.z);
        acc.w += (a0.w + a1.w) + (a2.w + a3.w);
    }
    for (; j < cnt; j++) {
        int s = g_csr[start + j];
        float4 a = hs4[(size_t)s * 64 + t];
        acc.x += a.x; acc.y += a.y; acc.z += a.z; acc.w += a.w;
    }
    const float dv = g_dinv[n];
    const float4 bb = ((const float4*)(g_bpad + layer * HSP))[t];
    float v[4];
    v[0] = dv * acc.x + bb.x;
    v[1] = dv * acc.y + bb.y;
    v[2] = dv * acc.z + bb.z;
    v[3] = dv * acc.w + bb.w;
    const int c0 = t * 4;

    if (!last) {
        BfPack hi, lo;
        #pragma unroll
        for (int i = 0; i < 4; i++) {
            float r = v[i] > 0.0f ? v[i] : 0.0f;
            if (c0 + i >= HID) r = 0.0f;                // keep K-padding zero
            split_bf16(r, hi.h[i], lo.h[i]);
        }
        *(uint2*)(g_ahi + (size_t)n * KP + c0) = hi.u;
        *(uint2*)(g_alo + (size_t)n * KP + c0) = lo.u;
        return;
    }
    // log_softmax over the 64-thread group (2 warps, named barriers)
    __shared__ float smax[4][2];
    __shared__ float ssum[4][2];
    float m = -INFINITY;
    #pragma unroll
    for (int i = 0; i < 4; i++)
        if (c0 + i < HID) m = fmaxf(m, v[i]);
    #pragma unroll
    for (int o = 16; o > 0; o >>= 1) m = fmaxf(m, __shfl_xor_sync(0xffffffffu, m, o));
    if (lane == 0) smax[g][wig] = m;
    asm volatile("bar.sync %0, 64;" :: "r"(1 + g) : "memory");
    const float gm = fmaxf(smax[g][0], smax[g][1]);
    float s = 0.0f;
    #pragma unroll
    for (int i = 0; i < 4; i++)
        if (c0 + i < HID) s += expf(v[i] - gm);
    #pragma unroll
    for (int o = 16; o > 0; o >>= 1) s += __shfl_xor_sync(0xffffffffu, s, o);
    if (lane == 0) ssum[g][wig] = s;
    asm volatile("bar.sync %0, 64;" :: "r"(1 + g) : "memory");
    const float lse = logf(ssum[g][0] + ssum[g][1]);
    #pragma unroll
    for (int i = 0; i < 4; i++)
        if (c0 + i < HID) out[(size_t)n * HID + c0 + i] = v[i] - gm - lse;
}

// ---------------- launch ----------------------------------------------------
extern "C" void kernel_launch(void* const* d_in, const int* in_sizes, int n_in,
                              void* d_out, int out_size) {
    const float* x  = (const float*)d_in[0];
    const int*   ei = (const int*)  d_in[1];
    const float* W1 = (const float*)d_in[2];
    const float* b1 = (const float*)d_in[3];
    const float* W2 = (const float*)d_in[4];
    const float* b2 = (const float*)d_in[5];
    const float* W3 = (const float*)d_in[6];
    const float* b3 = (const float*)d_in[7];
    const float* W4 = (const float*)d_in[8];
    const float* b4 = (const float*)d_in[9];
    float* out = (float*)d_out;

    const int HIDc = in_sizes[3];                 // 246
    const int F_IN = in_sizes[2] / HIDc;          // 256
    const int N    = in_sizes[0] / F_IN;          // 50000
    const int E    = in_sizes[1] / 2;             // 320000

    // edge preprocessing -> CSR
    int nwords = (2 * E < 4096) ? 2 * E : 4096;
    detect_k<<<1, 256>>>(ei, nwords);
    zero_cnt_k<<<(N + 255) / 256, 256>>>(N);
    convert_count_k<<<(E + 255) / 256, 256>>>(ei, E);
    dinv_k<<<(N + 255) / 256, 256>>>(N);
    int nb = (N + 255) / 256;
    scan1_k<<<nb, 256>>>(N);
    scan2_k<<<1, 256>>>(nb);
    scan3_k<<<nb, 256>>>(N);
    fill_csr_k<<<(E + 255) / 256, 256>>>(E);

    // conversions
    conv_x_k<<<(N * F_IN + 255) / 256, 256>>>(x, N * F_IN);
    conv_w_k<<<(KP * KP + 255) / 256, 256>>>(W1, F_IN, 0);
    conv_w_k<<<(KP * KP + 255) / 256, 256>>>(W2, HIDc, 1);
    conv_w_k<<<(KP * KP + 255) / 256, 256>>>(W3, HIDc, 2);
    conv_w_k<<<(KP * KP + 255) / 256, 256>>>(W4, HIDc, 3);
    pad_b_k<<<1, 256>>>(b1, 0);
    pad_b_k<<<1, 256>>>(b2, 1);
    pad_b_k<<<1, 256>>>(b3, 2);
    pad_b_k<<<1, 256>>>(b4, 3);

    dim3 ggrid(2, (N + BM - 1) / BM);             // (2, 391)
    const int gath_grid = (N + 3) / 4;            // 12500

    for (int layer = 0; layer < 4; layer++) {
        gemm_tc_k<<<ggrid, 256>>>(N, layer);
        gather_k<<<gath_grid, 256>>>(layer == 3 ? 1 : 0, layer, out, N);
    }
    (void)n_in; (void)out_size;
}

// round 7
// speedup vs baseline: 3.4941x; 1.1049x over previous
#include <cuda_runtime.h>
#include <cuda_bf16.h>
#include <math.h>
#include <stdint.h>

#define HID   246
#define NMAX  50000
#define EMAX  320000
#define KP    256            // padded K (activation row stride)
#define HSP   256            // padded g_hs row stride (floats)
#define NBLK  ((NMAX + 255) / 256)

// ---------------- device-global scratch (no allocation allowed) ------------
__device__ __align__(16) float g_dinv[NMAX];
__device__ __align__(16) float g_hs  [NMAX * HSP];          // (A@W)*dinv, padded
__device__ __align__(16) __nv_bfloat16 g_ahi[NMAX * KP];    // activation hi
__device__ __align__(16) __nv_bfloat16 g_alo[NMAX * KP];    // activation lo
__device__ __align__(16) __nv_bfloat16 g_whi[4 * KP * KP];  // W hi [k][n] padded
__device__ __align__(16) __nv_bfloat16 g_wlo[4 * KP * KP];  // W lo
__device__ __align__(16) float g_bpad[4 * HSP];             // padded biases
__device__ int g_src[EMAX];
__device__ int g_dst[EMAX];
__device__ int g_cnt[NMAX];
__device__ int g_rsI[NMAX];
__device__ int g_rowstart[NMAX];
__device__ int g_cursor[NMAX];
__device__ int g_csr[EMAX];
__device__ int g_bsum[NBLK];
__device__ int g_boff[NBLK];
__device__ int g_is64;

// ---------------- helpers ---------------------------------------------------
__device__ __forceinline__ void split_bf16(float v, __nv_bfloat16& hi, __nv_bfloat16& lo) {
    hi = __float2bfloat16(v);
    lo = __float2bfloat16(v - __bfloat162float(hi));
}
__device__ __forceinline__ unsigned smaddr(const void* p) {
    return (unsigned)__cvta_generic_to_shared(p);
}
__device__ __forceinline__ void ldsm_x4(unsigned a, unsigned& r0, unsigned& r1,
                                        unsigned& r2, unsigned& r3) {
    asm volatile("ldmatrix.sync.aligned.m8n8.x4.shared.b16 {%0,%1,%2,%3}, [%4];"
                 : "=r"(r0), "=r"(r1), "=r"(r2), "=r"(r3) : "r"(a));
}
__device__ __forceinline__ void ldsm_x4_t(unsigned a, unsigned& r0, unsigned& r1,
                                          unsigned& r2, unsigned& r3) {
    asm volatile("ldmatrix.sync.aligned.m8n8.x4.trans.shared.b16 {%0,%1,%2,%3}, [%4];"
                 : "=r"(r0), "=r"(r1), "=r"(r2), "=r"(r3) : "r"(a));
}
__device__ __forceinline__ void mma_bf16(float* c, const unsigned* a, unsigned b0, unsigned b1) {
    asm volatile("mma.sync.aligned.m16n8k16.row.col.f32.bf16.bf16.f32 "
                 "{%0,%1,%2,%3}, {%4,%5,%6,%7}, {%8,%9}, {%0,%1,%2,%3};"
                 : "+f"(c[0]), "+f"(c[1]), "+f"(c[2]), "+f"(c[3])
                 : "r"(a[0]), "r"(a[1]), "r"(a[2]), "r"(a[3]), "r"(b0), "r"(b1));
}
__device__ __forceinline__ void cpa16(unsigned dst, const void* src) {
    asm volatile("cp.async.cg.shared.global [%0], [%1], 16;" :: "r"(dst), "l"(src));
}
__device__ __forceinline__ void cpa16z(unsigned dst, const void* src, int srcbytes) {
    asm volatile("cp.async.cg.shared.global [%0], [%1], 16, %2;"
                 :: "r"(dst), "l"(src), "r"(srcbytes));
}
#define CPA_COMMIT() asm volatile("cp.async.commit_group;" ::: "memory")
#define CPA_WAIT(n)  asm volatile("cp.async.wait_group %0;" :: "n"(n) : "memory")

// ---------------- edge preprocessing ---------------------------------------
// grid = NBLK blocks: every block zeroes its g_cnt slice; block 0 also detects
// edge dtype (int64 little-endian with values < 2^31 => odd words all zero).
__global__ void detect_zero_k(const int* __restrict__ w, int nwords, int N) {
    int i = blockIdx.x * blockDim.x + threadIdx.x;
    if (i < N) g_cnt[i] = 0;
    if (blockIdx.x == 0) {
        __shared__ int any;
        if (threadIdx.x == 0) any = 0;
        __syncthreads();
        for (int j = 2 * threadIdx.x + 1; j < nwords; j += 2 * blockDim.x)
            if (w[j] != 0) any = 1;
        __syncthreads();
        if (threadIdx.x == 0) g_is64 = (any == 0) ? 1 : 0;
    }
}
__global__ void convert_count_k(const int* __restrict__ w, int E) {
    int i = blockIdx.x * blockDim.x + threadIdx.x;
    if (i >= E) return;
    int s, d;
    if (g_is64) { s = w[2 * i]; d = w[2 * (E + i)]; }
    else        { s = w[i];     d = w[E + i]; }
    g_src[i] = s;
    g_dst[i] = d;
    atomicAdd(&g_cnt[d], 1);
}
__global__ void scan1_k(int N) {
    __shared__ int sh[256];
    int i = blockIdx.x * 256 + threadIdx.x;
    int v = (i < N) ? g_cnt[i] : 0;
    sh[threadIdx.x] = v;
    __syncthreads();
    for (int o = 1; o < 256; o <<= 1) {
        int t = (threadIdx.x >= o) ? sh[threadIdx.x - o] : 0;
        __syncthreads();
        sh[threadIdx.x] += t;
        __syncthreads();
    }
    if (i < N) g_rsI[i] = sh[threadIdx.x];
    if (threadIdx.x == 255) g_bsum[blockIdx.x] = sh[255];
}
__global__ void scan2_k(int NB) {
    __shared__ int sh[256];
    int v = (threadIdx.x < NB) ? g_bsum[threadIdx.x] : 0;
    sh[threadIdx.x] = v;
    __syncthreads();
    for (int o = 1; o < 256; o <<= 1) {
        int t = (threadIdx.x >= o) ? sh[threadIdx.x - o] : 0;
        __syncthreads();
        sh[threadIdx.x] += t;
        __syncthreads();
    }
    if (threadIdx.x < NB) g_boff[threadIdx.x] = sh[threadIdx.x] - v;
}
__global__ void scan3_dinv_k(int N) {
    int i = blockIdx.x * blockDim.x + threadIdx.x;
    if (i >= N) return;
    int cnt = g_cnt[i];
    int ex = g_rsI[i] - cnt + g_boff[i >> 8];
    g_rowstart[i] = ex;
    g_cursor[i]   = ex;
    g_dinv[i]     = rsqrtf((float)(cnt + 1));
}
__global__ void fill_csr_k(int E) {
    int e = blockIdx.x * blockDim.x + threadIdx.x;
    if (e >= E) return;
    int d = g_dst[e];
    int pos = atomicAdd(&g_cursor[d], 1);
    g_csr[pos] = g_src[e];
}

// ---------------- conversions ----------------------------------------------
__global__ void conv_x_k(const float* __restrict__ x, int total) {
    int i = blockIdx.x * blockDim.x + threadIdx.x;
    if (i >= total) return;
    split_bf16(x[i], g_ahi[i], g_alo[i]);
}
// all 4 weight slabs in one launch: W [K,246] fp32 -> [256 k][256 n] hi/lo
__global__ void conv_w4_k(const float* __restrict__ W1, const float* __restrict__ W2,
                          const float* __restrict__ W3, const float* __restrict__ W4,
                          int K1) {
    int i = blockIdx.x * blockDim.x + threadIdx.x;
    if (i >= 4 * KP * KP) return;
    int layer = i >> 16;
    int j = i & 0xFFFF;
    int r = j >> 8, c = j & 255;
    const float* W = (layer == 0) ? W1 : (layer == 1) ? W2 : (layer == 2) ? W3 : W4;
    int K = (layer == 0) ? K1 : HID;
    float v = (r < K && c < HID) ? W[r * HID + c] : 0.0f;
    __nv_bfloat16 hi, lo;
    split_bf16(v, hi, lo);
    g_whi[i] = hi;
    g_wlo[i] = lo;
}
__global__ void pad_b4_k(const float* __restrict__ b1, const float* __restrict__ b2,
                         const float* __restrict__ b3, const float* __restrict__ b4) {
    int c = threadIdx.x;
    const float* bs[4] = {b1, b2, b3, b4};
    #pragma unroll
    for (int l = 0; l < 4; l++)
        g_bpad[l * HSP + c] = (c < HID) ? bs[l][c] : 0.0f;
}

// ---------------- bf16x3 tensor-core GEMM (mma.sync, 3-stage cp.async) -----
// g_hs[row][0..255] = (A @ W) * dinv[row]; K' = 3*256 = 768, chunks of 32.
// Tile 128x128, 8 warps (4 M x 2 N), warp tile 32x64.
#define BM 128
#define BN 128
#define BKB 32
#define NCHUNK 24
#define NSTAGE 3
#define A_STRIDE 40
#define B_STRIDE 136
#define A_ST_BYTES (BM * A_STRIDE * 2)               // 10240
#define B_ST_BYTES (BKB * B_STRIDE * 2)              // 8704
#define GEMM_SMEM (NSTAGE * (A_ST_BYTES + B_ST_BYTES))  // 56832

__global__ __launch_bounds__(256, 2) void gemm_tc_k(int M, int layer) {
    extern __shared__ char dsm[];
    __nv_bfloat16 (*As)[BM][A_STRIDE] =
        (__nv_bfloat16 (*)[BM][A_STRIDE])dsm;
    __nv_bfloat16 (*Bs)[BKB][B_STRIDE] =
        (__nv_bfloat16 (*)[BKB][B_STRIDE])(dsm + NSTAGE * A_ST_BYTES);
    const int tid  = threadIdx.x;
    const int lane = tid & 31;
    const int wid  = tid >> 5;
    const int wm   = (wid & 3) * 32;
    const int wn   = (wid >> 2) * 64;
    const int row0 = blockIdx.y * BM;
    const int col0 = blockIdx.x * BN;
    const __nv_bfloat16* wbase_hi = g_whi + layer * KP * KP;
    const __nv_bfloat16* wbase_lo = g_wlo + layer * KP * KP;

    const int ar0 = tid >> 2,  aq0 = tid & 3;
    const int ar1 = (tid + 256) >> 2, aq1 = tid & 3;
    const int br0 = tid >> 4,  bq0 = tid & 15;
    const int br1 = (tid + 256) >> 4, bq1 = tid & 15;

    float acc[2][8][4];
    #pragma unroll
    for (int a = 0; a < 2; a++)
        #pragma unroll
        for (int b = 0; b < 8; b++)
            #pragma unroll
            for (int c = 0; c < 4; c++) acc[a][b][c] = 0.0f;

    auto issue = [&](int chunk, int buf) {
        const int p    = chunk >> 3;                 // 0 hi*hi, 1 hi*lo, 2 lo*hi
        const int ksrc = (chunk & 7) * BKB;
        const __nv_bfloat16* Asrc = (p < 2) ? g_ahi : g_alo;
        const __nv_bfloat16* Bsrc = (p == 1) ? wbase_lo : wbase_hi;
        int gr0 = row0 + ar0, gr1 = row0 + ar1;
        cpa16z(smaddr(&As[buf][ar0][aq0 * 8]),
               Asrc + (size_t)gr0 * KP + ksrc + aq0 * 8, gr0 < M ? 16 : 0);
        cpa16z(smaddr(&As[buf][ar1][aq1 * 8]),
               Asrc + (size_t)gr1 * KP + ksrc + aq1 * 8, gr1 < M ? 16 : 0);
        cpa16(smaddr(&Bs[buf][br0][bq0 * 8]),
              Bsrc + (size_t)(ksrc + br0) * KP + col0 + bq0 * 8);
        cpa16(smaddr(&Bs[buf][br1][bq1 * 8]),
              Bsrc + (size_t)(ksrc + br1) * KP + col0 + bq1 * 8);
        CPA_COMMIT();
    };

    issue(0, 0);
    issue(1, 1);
    issue(2, 2);
    #pragma unroll 1
    for (int c = 0; c < NCHUNK; c++) {
        const int buf = c % NSTAGE;
        if (c <= NCHUNK - 3)      CPA_WAIT(2);
        else if (c == NCHUNK - 2) CPA_WAIT(1);
        else                      CPA_WAIT(0);
        __syncthreads();
        #pragma unroll
        for (int ks = 0; ks < 2; ks++) {
            const int kk = ks * 16;
            unsigned af[2][4], bf[4][4];
            #pragma unroll
            for (int mt = 0; mt < 2; mt++) {
                int r = wm + mt * 16 + (lane & 7) + (lane & 8);
                int cc = kk + ((lane & 16) ? 8 : 0);
                ldsm_x4(smaddr(&As[buf][r][cc]), af[mt][0], af[mt][1], af[mt][2], af[mt][3]);
            }
            #pragma unroll
            for (int nt = 0; nt < 4; nt++) {
                int r = kk + (lane & 7) + (lane & 8);
                int cc = wn + nt * 16 + ((lane & 16) ? 8 : 0);
                ldsm_x4_t(smaddr(&Bs[buf][r][cc]), bf[nt][0], bf[nt][1], bf[nt][2], bf[nt][3]);
            }
            #pragma unroll
            for (int mt = 0; mt < 2; mt++)
                #pragma unroll
                for (int j = 0; j < 8; j++)
                    mma_bf16(acc[mt][j], af[mt], bf[j >> 1][(j & 1) * 2],
                             bf[j >> 1][(j & 1) * 2 + 1]);
        }
        __syncthreads();
        if (c + NSTAGE < NCHUNK) issue(c + NSTAGE, buf);
    }
    // epilogue: scale by dinv[row]; unconditional col stores (padded g_hs)
    const int gID = lane >> 2, tig = lane & 3;
    #pragma unroll
    for (int mt = 0; mt < 2; mt++) {
        #pragma unroll
        for (int half = 0; half < 2; half++) {
            int gr = row0 + wm + mt * 16 + gID + half * 8;
            if (gr >= M) continue;
            float dv = g_dinv[gr];
            #pragma unroll
            for (int j = 0; j < 8; j++) {
                int gc = col0 + wn + j * 8 + tig * 2;
                float2 v = make_float2(acc[mt][j][half * 2 + 0] * dv,
                                       acc[mt][j][half * 2 + 1] * dv);
                *(float2*)&g_hs[(size_t)gr * HSP + gc] = v;
            }
        }
    }
}

// ---------------- fused gather + bias (+relu+split | +log_softmax) ---------
// 4 nodes/block, 64 threads/node, float4 per thread.
union BfPack { __nv_bfloat16 h[4]; uint2 u; };

__global__ __launch_bounds__(256) void gather_k(int last, int layer,
                                                float* __restrict__ out, int N) {
    const int g = threadIdx.x >> 6;
    const int t = threadIdx.x & 63;
    const int lane = threadIdx.x & 31;
    const int wig = (threadIdx.x >> 5) & 1;
    const int n = blockIdx.x * 4 + g;
    if (n >= N) return;

    const float4* hs4 = (const float4*)g_hs;
    float4 acc = __ldg(&hs4[(size_t)n * 64 + t]);       // self loop (pre-scaled)
    const int start = g_rowstart[n];
    const int cnt   = g_cnt[n];
    int j = 0;
    for (; j + 4 <= cnt; j += 4) {
        int s0 = __ldg(&g_csr[start + j]);
        int s1 = __ldg(&g_csr[start + j + 1]);
        int s2 = __ldg(&g_csr[start + j + 2]);
        int s3 = __ldg(&g_csr[start + j + 3]);
        float4 a0 = __ldg(&hs4[(size_t)s0 * 64 + t]);
        float4 a1 = __ldg(&hs4[(size_t)s1 * 64 + t]);
        float4 a2 = __ldg(&hs4[(size_t)s2 * 64 + t]);
        float4 a3 = __ldg(&hs4[(size_t)s3 * 64 + t]);
        acc.x += (a0.x + a1.x) + (a2.x + a3.x);
        acc.y += (a0.y + a1.y) + (a2.y + a3.y);
        acc.z += (a0.z + a1.z) + (a2.z + a3.z);
        acc.w += (a0.w + a1.w) + (a2.w + a3.w);
    }
    for (; j < cnt; j++) {
        int s = __ldg(&g_csr[start + j]);
        float4 a = __ldg(&hs4[(size_t)s * 64 + t]);
        acc.x += a.x; acc.y += a.y; acc.z += a.z; acc.w += a.w;
    }
    const float dv = g_dinv[n];
    const float4 bb = ((const float4*)(g_bpad + layer * HSP))[t];
    float v[4];
    v[0] = dv * acc.x + bb.x;
    v[1] = dv * acc.y + bb.y;
    v[2] = dv * acc.z + bb.z;
    v[3] = dv * acc.w + bb.w;
    const int c0 = t * 4;

    if (!last) {
        BfPack hi, lo;
        #pragma unroll
        for (int i = 0; i < 4; i++) {
            float r = v[i] > 0.0f ? v[i] : 0.0f;
            if (c0 + i >= HID) r = 0.0f;                // keep K-padding zero
            split_bf16(r, hi.h[i], lo.h[i]);
        }
        *(uint2*)(g_ahi + (size_t)n * KP + c0) = hi.u;
        *(uint2*)(g_alo + (size_t)n * KP + c0) = lo.u;
        return;
    }
    // log_softmax over the 64-thread group (2 warps, named barriers)
    __shared__ float smax[4][2];
    __shared__ float ssum[4][2];
    float m = -INFINITY;
    #pragma unroll
    for (int i = 0; i < 4; i++)
        if (c0 + i < HID) m = fmaxf(m, v[i]);
    #pragma unroll
    for (int o = 16; o > 0; o >>= 1) m = fmaxf(m, __shfl_xor_sync(0xffffffffu, m, o));
    if (lane == 0) smax[g][wig] = m;
    asm volatile("bar.sync %0, 64;" :: "r"(1 + g) : "memory");
    const float gm = fmaxf(smax[g][0], smax[g][1]);
    float s = 0.0f;
    #pragma unroll
    for (int i = 0; i < 4; i++)
        if (c0 + i < HID) s += expf(v[i] - gm);
    #pragma unroll
    for (int o = 16; o > 0; o >>= 1) s += __shfl_xor_sync(0xffffffffu, s, o);
    if (lane == 0) ssum[g][wig] = s;
    asm volatile("bar.sync %0, 64;" :: "r"(1 + g) : "memory");
    const float lse = logf(ssum[g][0] + ssum[g][1]);
    #pragma unroll
    for (int i = 0; i < 4; i++)
        if (c0 + i < HID) out[(size_t)n * HID + c0 + i] = v[i] - gm - lse;
}

// ---------------- launch ----------------------------------------------------
extern "C" void kernel_launch(void* const* d_in, const int* in_sizes, int n_in,
                              void* d_out, int out_size) {
    const float* x  = (const float*)d_in[0];
    const int*   ei = (const int*)  d_in[1];
    const float* W1 = (const float*)d_in[2];
    const float* b1 = (const float*)d_in[3];
    const float* W2 = (const float*)d_in[4];
    const float* b2 = (const float*)d_in[5];
    const float* W3 = (const float*)d_in[6];
    const float* b3 = (const float*)d_in[7];
    const float* W4 = (const float*)d_in[8];
    const float* b4 = (const float*)d_in[9];
    float* out = (float*)d_out;

    const int HIDc = in_sizes[3];                 // 246
    const int F_IN = in_sizes[2] / HIDc;          // 256
    const int N    = in_sizes[0] / F_IN;          // 50000
    const int E    = in_sizes[1] / 2;             // 320000

    cudaFuncSetAttribute(gemm_tc_k,
                         cudaFuncAttributeMaxDynamicSharedMemorySize, GEMM_SMEM);

    // edge preprocessing -> CSR
    int nwords = (2 * E < 4096) ? 2 * E : 4096;
    int nb = (N + 255) / 256;
    detect_zero_k<<<nb, 256>>>(ei, nwords, N);
    convert_count_k<<<(E + 255) / 256, 256>>>(ei, E);
    scan1_k<<<nb, 256>>>(N);
    scan2_k<<<1, 256>>>(nb);
    scan3_dinv_k<<<nb, 256>>>(N);
    fill_csr_k<<<(E + 255) / 256, 256>>>(E);

    // conversions
    conv_x_k<<<(N * F_IN + 255) / 256, 256>>>(x, N * F_IN);
    conv_w4_k<<<(4 * KP * KP + 255) / 256, 256>>>(W1, W2, W3, W4, F_IN);
    pad_b4_k<<<1, 256>>>(b1, b2, b3, b4);

    dim3 ggrid(2, (N + BM - 1) / BM);             // (2, 391)
    const int gath_grid = (N + 3) / 4;            // 12500

    for (int layer = 0; layer < 4; layer++) {
        gemm_tc_k<<<ggrid, 256, GEMM_SMEM>>>(N, layer);
        gather_k<<<gath_grid, 256>>>(layer == 3 ? 1 : 0, layer, out, N);
    }
    (void)n_in; (void)out_size;
}